// round 11
// baseline (speedup 1.0000x reference)
#include <cuda_runtime.h>
#include <cuda_fp16.h>
#include <math.h>
#include <stdint.h>

#define NN 2048      // nodes
#define CXH 8192     // 2*64*64 columns of [x|h]
#define C1  4096     // 64*64
#define KD  2048     // GEMM K
#define FSTR 392     // padded half-stride for projection smem rows (384+8)
#define PN  8        // nodes per projection CTA

// ---------------- device scratch ----------------
__device__ float g_dinv[NN];
__device__ float g_XH [(size_t)NN * CXH];
__device__ float g_A1 [(size_t)NN * CXH];
__device__ float g_A2 [(size_t)NN * CXH];
__device__ float g_RH [(size_t)NN * C1];
__device__ float g_AR1[(size_t)NN * C1];
__device__ float g_AR2[(size_t)NN * C1];
__device__ float g_U  [(size_t)NN * C1];
__device__ __half g_Wruh[128 * 384];         // fp16, [n][k], k = s*64+f permuted
__device__ __half g_Wch [64 * 384];
__device__ __half g_Ah [(size_t)NN * KD];    // fp16 adjT, [m][k]
__device__ __half g_Bh [(size_t)CXH * KD];   // fp16 B operand [c][k] (stream-reused)

// ---------------- helpers ----------------
__device__ __forceinline__ uint32_t smem_u32(const void* p) {
    uint32_t a;
    asm("{ .reg .u64 t; cvta.to.shared.u64 t, %1; cvt.u32.u64 %0, t; }" : "=r"(a) : "l"(p));
    return a;
}
__device__ __forceinline__ void cpasync16(uint32_t dst, const void* src) {
    asm volatile("cp.async.cg.shared.global [%0], [%1], 16;" :: "r"(dst), "l"(src));
}
__device__ __forceinline__ void ldsm4(uint32_t* r, uint32_t addr) {
    asm volatile("ldmatrix.sync.aligned.m8n8.x4.shared.b16 {%0,%1,%2,%3}, [%4];"
        : "=r"(r[0]), "=r"(r[1]), "=r"(r[2]), "=r"(r[3]) : "r"(addr));
}
__device__ __forceinline__ void mma16816(float* d, const uint32_t* a, const uint32_t* b) {
    asm volatile("mma.sync.aligned.m16n8k16.row.col.f32.f16.f16.f32 "
        "{%0,%1,%2,%3}, {%4,%5,%6,%7}, {%8,%9}, {%0,%1,%2,%3};"
        : "+f"(d[0]), "+f"(d[1]), "+f"(d[2]), "+f"(d[3])
        : "r"(a[0]), "r"(a[1]), "r"(a[2]), "r"(a[3]), "r"(b[0]), "r"(b[1]));
}
// fp16-accumulate variant: D,C are 2 .f16x2 regs
__device__ __forceinline__ void mma16816h(uint32_t* d, const uint32_t* a, const uint32_t* b) {
    asm volatile("mma.sync.aligned.m16n8k16.row.col.f16.f16.f16.f16 "
        "{%0,%1}, {%2,%3,%4,%5}, {%6,%7}, {%0,%1};"
        : "+r"(d[0]), "+r"(d[1])
        : "r"(a[0]), "r"(a[1]), "r"(a[2]), "r"(a[3]), "r"(b[0]), "r"(b[1]));
}
__device__ __forceinline__ int wsrc_row(int k) {
    int s = k >> 6, f = k & 63;
    return (s < 3) ? (f * 3 + s) : (192 + f * 3 + (s - 3));
}

// ---------------- launch 1: row sums ----------------
__global__ void rowsum_kernel(const float* __restrict__ adj) {
    int m = blockIdx.x;
    const float* row = adj + (size_t)m * NN;
    float s = 0.f;
    for (int i = threadIdx.x; i < NN; i += 256) s += row[i];
    #pragma unroll
    for (int o = 16; o; o >>= 1) s += __shfl_down_sync(0xffffffffu, s, o);
    __shared__ float sm[8];
    if ((threadIdx.x & 31) == 0) sm[threadIdx.x >> 5] = s;
    __syncthreads();
    if (threadIdx.x < 8) {
        float v = sm[threadIdx.x];
        #pragma unroll
        for (int o = 4; o; o >>= 1) v += __shfl_down_sync(0xffu, v, o);
        if (threadIdx.x == 0) g_dinv[m] = 1.0f / (v + 1.0f);
    }
}

// ---------------- launch 2: pack XH + build fp16 transposed weights ----------------
__global__ void pack_permW(const float* __restrict__ x, const float* __restrict__ h,
                           const float* __restrict__ Wru, const float* __restrict__ Wc) {
    int bid = blockIdx.x;
    int t = threadIdx.x;
    if (bid < 16384) {
        int idx4 = bid * 256 + t;
        int m = idx4 >> 11;
        int c = (idx4 & 2047) * 4;
        const float* src;
        if (c < C1) { int b = c >> 6, f = c & 63; src = x + (size_t)b * (NN * 64) + m * 64 + f; }
        else { int cc = c - C1; int b = cc >> 6, f = cc & 63; src = h + (size_t)b * (NN * 64) + m * 64 + f; }
        *(float4*)&g_XH[(size_t)m * CXH + c] = *(const float4*)src;
    } else {
        int idx = (bid - 16384) * 256 + t;
        if (idx < 128 * 384) {
            int n = idx / 384, k = idx % 384;
            g_Wruh[n * 384 + k] = __float2half_rn(Wru[wsrc_row(k) * 128 + n]);
        } else if (idx < 128 * 384 + 64 * 384) {
            int j = idx - 128 * 384;
            int n = j / 384, k = j % 384;
            g_Wch[n * 384 + k] = __float2half_rn(Wc[wsrc_row(k) * 64 + n]);
        }
    }
}

// ---------------- launch 3: build fp16 adjT + fp16 transpose of XH (fused) ----------------
__global__ void conv1(const float* __restrict__ adj) {
    __shared__ float tile[64][65];
    int bid = blockIdx.x;
    int t = threadIdx.x;
    if (bid < 1024) {
        __shared__ float sdinv[64];
        int k0 = (bid >> 5) * 64, m0 = (bid & 31) * 64;
        if (t < 64) sdinv[t] = g_dinv[k0 + t];
        #pragma unroll
        for (int i = 0; i < 16; i++) {
            int q = t + 256 * i; int r = q >> 6, c = q & 63;
            tile[r][c] = adj[(size_t)(k0 + r) * NN + m0 + c];
        }
        __syncthreads();
        #pragma unroll
        for (int i = 0; i < 16; i++) {
            int q = t + 256 * i; int f = q >> 6, n = q & 63;
            int kk = k0 + n, mm = m0 + f;
            float v = tile[n][f];
            if (kk == mm) v += 1.0f;
            g_Ah[(size_t)mm * KD + kk] = __float2half_rn(v * sdinv[n]);
        }
    } else {
        int tb = bid - 1024;                   // 4096 blocks
        int c0 = (tb & 127) * 64, k0 = (tb >> 7) * 64;
        #pragma unroll
        for (int i = 0; i < 16; i++) {
            int q = t + 256 * i; int r = q >> 6, c = q & 63;
            tile[r][c] = g_XH[(size_t)(k0 + r) * CXH + c0 + c];
        }
        __syncthreads();
        #pragma unroll
        for (int i = 0; i < 16; i++) {
            int q = t + 256 * i; int f = q >> 6, n = q & 63;
            g_Bh[(size_t)(c0 + f) * KD + (k0 + n)] = __float2half_rn(tile[n][f]);
        }
    }
}

// ---------------- fp16 transpose: dst[c][k] = fp16(src[k][c]) ----------------
__global__ void trans_f16(const float* __restrict__ src, __half* __restrict__ dst, int Ncols) {
    __shared__ float tile[64][65];
    int k0 = blockIdx.y * 64, c0 = blockIdx.x * 64;
    int t = threadIdx.x;
    #pragma unroll
    for (int i = 0; i < 16; i++) {
        int q = t + 256 * i; int r = q >> 6, c = q & 63;
        tile[r][c] = src[(size_t)(k0 + r) * Ncols + c0 + c];
    }
    __syncthreads();
    #pragma unroll
    for (int i = 0; i < 16; i++) {
        int q = t + 256 * i; int f = q >> 6, n = q & 63;
        dst[(size_t)(c0 + f) * KD + (k0 + n)] = __float2half_rn(tile[n][f]);
    }
}

// ---------------- HMMA GEMM (fp16 dual-accumulate): Cout = alpha*(A @ B^T) + beta*Cin ----------------
// 512 threads, 16 warps, CTA tile 128x256, warp tile 64x32, BK=32.
// Two fp16 accumulator sets alternating per k16 (each sees K=1024); fp32 combine in epilogue.
#define ROWB 80
#define ASZ  (128 * ROWB)
#define BSZ  (256 * ROWB)
#define STB  (ASZ + BSZ)
#define GSMEM (4 * STB)
#define NST  (KD / 32)            // 64

__global__ __launch_bounds__(512, 1)
void gemm_mma(const __half* __restrict__ A, const __half* __restrict__ B,
              const float* __restrict__ Cin, float* __restrict__ Cout,
              int Ncols, float alpha, float beta) {
    extern __shared__ char smem[];
    uint32_t sbase = smem_u32(smem);
    int t = threadIdx.x;
    int lane = t & 31, wid = t >> 5;
    int m0 = blockIdx.y * 128;
    int n0 = blockIdx.x * 256;
    int wm = (wid & 1) * 64;
    int wn = (wid >> 1) * 32;

    uint32_t aOff[4], bOff[2];
    #pragma unroll
    for (int mt = 0; mt < 4; mt++)
        aOff[mt] = (uint32_t)((wm + mt * 16 + (lane & 15)) * ROWB + (lane >> 4) * 16);
    #pragma unroll
    for (int np = 0; np < 2; np++)
        bOff[np] = (uint32_t)(ASZ + (wn + np * 16 + (lane & 7) + ((lane >> 4) << 3)) * ROWB
                              + ((lane >> 3) & 1) * 16);

    auto load_stage = [&](int s) {
        int slot = s & 3; int k0 = s * 32;
        uint32_t ab = sbase + slot * STB;
        const __half* gA = A + (size_t)m0 * KD + k0;
        const __half* gB = B + (size_t)n0 * KD + k0;
        #pragma unroll
        for (int i = 0; i < 3; i++) {
            int q = t + 512 * i;
            if (q < 512) {
                int r = q >> 2, c4 = q & 3;
                cpasync16(ab + r * ROWB + c4 * 16, gA + (size_t)r * KD + c4 * 8);
            } else {
                int qq = q - 512; int r = qq >> 2, c4 = qq & 3;
                cpasync16(ab + ASZ + r * ROWB + c4 * 16, gB + (size_t)r * KD + c4 * 8);
            }
        }
        asm volatile("cp.async.commit_group;" ::: "memory");
    };

    // two fp16 accumulator sets: [parity][mt][nt][2 x .f16x2]
    uint32_t accp[2][4][4][2] = {};

    load_stage(0); load_stage(1); load_stage(2);

    for (int s = 0; s < NST; ++s) {
        if (s <= NST - 3)      asm volatile("cp.async.wait_group 2;" ::: "memory");
        else if (s == NST - 2) asm volatile("cp.async.wait_group 1;" ::: "memory");
        else                   asm volatile("cp.async.wait_group 0;" ::: "memory");
        __syncthreads();

        uint32_t sb = sbase + (s & 3) * STB;
        #pragma unroll
        for (int k16 = 0; k16 < 2; k16++) {
            uint32_t a[4][4], b[2][4];
            #pragma unroll
            for (int mt = 0; mt < 4; mt++) ldsm4(a[mt], sb + aOff[mt] + k16 * 32);
            #pragma unroll
            for (int np = 0; np < 2; np++) ldsm4(b[np], sb + bOff[np] + k16 * 32);
            #pragma unroll
            for (int mt = 0; mt < 4; mt++)
                #pragma unroll
                for (int nt = 0; nt < 4; nt++)
                    mma16816h(accp[k16][mt][nt], a[mt], &b[nt >> 1][(nt & 1) * 2]);
        }

        if (s + 3 < NST) load_stage(s + 3);
    }

    bool has_cin = (Cin != nullptr);
    #pragma unroll
    for (int mt = 0; mt < 4; mt++) {
        #pragma unroll
        for (int nt = 0; nt < 4; nt++) {
            int m = m0 + wm + mt * 16 + (lane >> 2);
            int n = n0 + wn + nt * 8 + (lane & 3) * 2;
            size_t g0 = (size_t)m * Ncols + n;
            size_t g1 = g0 + (size_t)8 * Ncols;
            // combine the two fp16 partial sums in fp32
            float2 e0 = __half22float2(*(__half2*)&accp[0][mt][nt][0]);
            float2 e1 = __half22float2(*(__half2*)&accp[0][mt][nt][1]);
            float2 o0 = __half22float2(*(__half2*)&accp[1][mt][nt][0]);
            float2 o1 = __half22float2(*(__half2*)&accp[1][mt][nt][1]);
            float v0 = alpha * (e0.x + o0.x), v1 = alpha * (e0.y + o0.y);
            float v2 = alpha * (e1.x + o1.x), v3 = alpha * (e1.y + o1.y);
            if (has_cin) {
                float2 c0 = *(const float2*)&Cin[g0];
                float2 c1 = *(const float2*)&Cin[g1];
                v0 += beta * c0.x; v1 += beta * c0.y;
                v2 += beta * c1.x; v3 += beta * c1.y;
            }
            float2 w0 = {v0, v1}, w1 = {v2, v3};
            *(float2*)&Cout[g0] = w0;
            *(float2*)&Cout[g1] = w1;
        }
    }
}

// ---------------- projection RU (multi-node): 8 nodes/CTA, 256 threads ----------------
#define WRU_B (128 * FSTR * 2)
#define FBUF_B (64 * FSTR * 2)
#define PRU_SMEM (WRU_B + 2 * FBUF_B)
__global__ __launch_bounds__(256)
void proj_ru_mma(const float* __restrict__ b_ru) {
    extern __shared__ char ps[];
    __half* Ws = (__half*)ps;                          // [128][FSTR]
    __half* F0 = (__half*)(ps + WRU_B);                // [64][FSTR] x2
    uint32_t wsb = smem_u32(Ws), fsb = smem_u32(F0);
    int t = threadIdx.x;
    int lane = t & 31, wid = t >> 5;
    int m0 = blockIdx.x * PN;
    int wm = (wid & 1) * 32, wn = (wid >> 1) * 32;

    #pragma unroll
    for (int j = 0; j < 24; j++) {
        int q = j * 256 + t;
        int n = q / 48, c = q % 48;
        *(uint4*)(Ws + n * FSTR + c * 8) = *(const uint4*)(g_Wruh + n * 384 + c * 8);
    }

    float4 r[24];
    auto ldF = [&](int m) {
        const float* segp[6] = {
            g_XH + (size_t)m * CXH,      g_A1 + (size_t)m * CXH,      g_A2 + (size_t)m * CXH,
            g_XH + (size_t)m * CXH + C1, g_A1 + (size_t)m * CXH + C1, g_A2 + (size_t)m * CXH + C1 };
        #pragma unroll
        for (int j = 0; j < 24; j++) {
            int q = j * 256 + t;
            int bb = q / 96, f4 = q % 96;
            int col = f4 * 4, s = col >> 6, f = col & 63;
            r[j] = *(const float4*)(segp[s] + bb * 64 + f);
        }
    };
    auto stF = [&](__half* buf) {
        #pragma unroll
        for (int j = 0; j < 24; j++) {
            int q = j * 256 + t;
            int bb = q / 96, col = (q % 96) * 4;
            __half2* d = (__half2*)(buf + bb * FSTR + col);
            d[0] = __floats2half2_rn(r[j].x, r[j].y);
            d[1] = __floats2half2_rn(r[j].z, r[j].w);
        }
    };

    uint32_t aRel[2], bOff[2];
    #pragma unroll
    for (int mt = 0; mt < 2; mt++)
        aRel[mt] = (wm + mt * 16 + (lane & 15)) * (FSTR * 2) + (lane >> 4) * 16;
    #pragma unroll
    for (int np = 0; np < 2; np++)
        bOff[np] = wsb + (wn + np * 16 + (lane & 7) + ((lane >> 4) << 3)) * (FSTR * 2)
                   + ((lane >> 3) & 1) * 16;

    ldF(m0);
    stF(F0);
    __syncthreads();

    for (int i = 0; i < PN; i++) {
        int m = m0 + i;
        if (i + 1 < PN) ldF(m + 1);

        uint32_t fb = fsb + (i & 1) * FBUF_B;
        float acc[2][4][4] = {};
        #pragma unroll
        for (int k = 0; k < 24; k++) {
            uint32_t a[2][4], b[2][4];
            ldsm4(a[0], fb + aRel[0] + k * 32);
            ldsm4(a[1], fb + aRel[1] + k * 32);
            ldsm4(b[0], bOff[0] + k * 32);
            ldsm4(b[1], bOff[1] + k * 32);
            #pragma unroll
            for (int mt = 0; mt < 2; mt++)
                #pragma unroll
                for (int nt = 0; nt < 4; nt++)
                    mma16816(acc[mt][nt], a[mt], &b[nt >> 1][(nt & 1) * 2]);
        }

        #pragma unroll
        for (int mt = 0; mt < 2; mt++) {
            #pragma unroll
            for (int nt = 0; nt < 4; nt++) {
                int brow = wm + mt * 16 + (lane >> 2);
                int o = wn + nt * 8 + (lane & 3) * 2;
                float bo0 = b_ru[o], bo1 = b_ru[o + 1];
                #pragma unroll
                for (int hi = 0; hi < 2; hi++) {
                    int bb = brow + hi * 8;
                    float v0 = 1.0f / (1.0f + expf(-(acc[mt][nt][hi * 2 + 0] + bo0)));
                    float v1 = 1.0f / (1.0f + expf(-(acc[mt][nt][hi * 2 + 1] + bo1)));
                    if (o < 64) {
                        float h0 = g_XH[(size_t)m * CXH + C1 + bb * 64 + o];
                        float h1 = g_XH[(size_t)m * CXH + C1 + bb * 64 + o + 1];
                        float rh0 = v0 * h0, rh1 = v1 * h1;
                        g_RH[(size_t)m * C1 + bb * 64 + o]     = rh0;
                        g_RH[(size_t)m * C1 + bb * 64 + o + 1] = rh1;
                        g_Bh[(size_t)(bb * 64 + o) * KD + m]     = __float2half_rn(rh0);
                        g_Bh[(size_t)(bb * 64 + o + 1) * KD + m] = __float2half_rn(rh1);
                    } else {
                        g_U[(size_t)m * C1 + bb * 64 + (o - 64)]     = v0;
                        g_U[(size_t)m * C1 + bb * 64 + (o - 64) + 1] = v1;
                    }
                }
            }
        }

        if (i + 1 < PN) stF((__half*)(ps + WRU_B + ((i + 1) & 1) * FBUF_B));
        __syncthreads();
    }
}

// ---------------- projection C + GRU combine (multi-node): 8 nodes/CTA ----------------
#define WC_B (64 * FSTR * 2)
#define PC_SMEM (WC_B + 2 * FBUF_B)
__global__ __launch_bounds__(256)
void proj_c_mma(const float* __restrict__ b_c, float* __restrict__ out) {
    extern __shared__ char ps[];
    __half* Ws = (__half*)ps;
    __half* F0 = (__half*)(ps + WC_B);
    uint32_t wsb = smem_u32(Ws), fsb = smem_u32(F0);
    int t = threadIdx.x;
    int lane = t & 31, wid = t >> 5;
    int m0 = blockIdx.x * PN;
    int wm = (wid & 1) * 32, wn = (wid >> 1) * 16;

    #pragma unroll
    for (int j = 0; j < 12; j++) {
        int q = j * 256 + t;
        int n = q / 48, c = q % 48;
        *(uint4*)(Ws + n * FSTR + c * 8) = *(const uint4*)(g_Wch + n * 384 + c * 8);
    }

    float4 r[24];
    auto ldF = [&](int m) {
        const float* segp[6] = {
            g_XH + (size_t)m * CXH, g_A1 + (size_t)m * CXH, g_A2 + (size_t)m * CXH,
            g_RH + (size_t)m * C1,  g_AR1 + (size_t)m * C1, g_AR2 + (size_t)m * C1 };
        #pragma unroll
        for (int j = 0; j < 24; j++) {
            int q = j * 256 + t;
            int bb = q / 96, f4 = q % 96;
            int col = f4 * 4, s = col >> 6, f = col & 63;
            r[j] = *(const float4*)(segp[s] + bb * 64 + f);
        }
    };
    auto stF = [&](__half* buf) {
        #pragma unroll
        for (int j = 0; j < 24; j++) {
            int q = j * 256 + t;
            int bb = q / 96, col = (q % 96) * 4;
            __half2* d = (__half2*)(buf + bb * FSTR + col);
            d[0] = __floats2half2_rn(r[j].x, r[j].y);
            d[1] = __floats2half2_rn(r[j].z, r[j].w);
        }
    };

    uint32_t aRel[2], bOff;
    #pragma unroll
    for (int mt = 0; mt < 2; mt++)
        aRel[mt] = (wm + mt * 16 + (lane & 15)) * (FSTR * 2) + (lane >> 4) * 16;
    bOff = wsb + (wn + (lane & 7) + ((lane >> 4) << 3)) * (FSTR * 2)
           + ((lane >> 3) & 1) * 16;

    ldF(m0);
    stF(F0);
    __syncthreads();

    for (int i = 0; i < PN; i++) {
        int m = m0 + i;
        if (i + 1 < PN) ldF(m + 1);

        uint32_t fb = fsb + (i & 1) * FBUF_B;
        float acc[2][2][4] = {};
        #pragma unroll
        for (int k = 0; k < 24; k++) {
            uint32_t a[2][4], b[4];
            ldsm4(a[0], fb + aRel[0] + k * 32);
            ldsm4(a[1], fb + aRel[1] + k * 32);
            ldsm4(b, bOff + k * 32);
            #pragma unroll
            for (int mt = 0; mt < 2; mt++)
                #pragma unroll
                for (int nt = 0; nt < 2; nt++)
                    mma16816(acc[mt][nt], a[mt], &b[nt * 2]);
        }

        #pragma unroll
        for (int mt = 0; mt < 2; mt++) {
            #pragma unroll
            for (int nt = 0; nt < 2; nt++) {
                int brow = wm + mt * 16 + (lane >> 2);
                int o = wn + nt * 8 + (lane & 3) * 2;
                float bo0 = b_c[o], bo1 = b_c[o + 1];
                #pragma unroll
                for (int hi = 0; hi < 2; hi++) {
                    int bb = brow + hi * 8;
                    float c0 = tanhf(acc[mt][nt][hi * 2 + 0] + bo0);
                    float c1 = tanhf(acc[mt][nt][hi * 2 + 1] + bo1);
                    float u0 = g_U[(size_t)m * C1 + bb * 64 + o];
                    float u1 = g_U[(size_t)m * C1 + bb * 64 + o + 1];
                    float h0 = g_XH[(size_t)m * CXH + C1 + bb * 64 + o];
                    float h1 = g_XH[(size_t)m * CXH + C1 + bb * 64 + o + 1];
                    float2 ov = {u0 * h0 + (1.0f - u0) * c0, u1 * h1 + (1.0f - u1) * c1};
                    *(float2*)&out[(size_t)bb * (NN * 64) + m * 64 + o] = ov;
                }
            }
        }

        if (i + 1 < PN) stF((__half*)(ps + WC_B + ((i + 1) & 1) * FBUF_B));
        __syncthreads();
    }
}

// ---------------- launch ----------------
extern "C" void kernel_launch(void* const* d_in, const int* in_sizes, int n_in,
                              void* d_out, int out_size) {
    const float* inputs = (const float*)d_in[0];
    const float* hx     = (const float*)d_in[1];
    const float* adj    = (const float*)d_in[2];
    const float* W_ru   = (const float*)d_in[3];
    const float* b_ru   = (const float*)d_in[4];
    const float* W_c    = (const float*)d_in[5];
    const float* b_c    = (const float*)d_in[6];
    float* out = (float*)d_out;

    float *p_XH, *p_A1, *p_A2, *p_RH, *p_AR1, *p_AR2;
    __half *p_Ah, *p_Bh;
    cudaGetSymbolAddress((void**)&p_XH,  g_XH);
    cudaGetSymbolAddress((void**)&p_A1,  g_A1);
    cudaGetSymbolAddress((void**)&p_A2,  g_A2);
    cudaGetSymbolAddress((void**)&p_RH,  g_RH);
    cudaGetSymbolAddress((void**)&p_AR1, g_AR1);
    cudaGetSymbolAddress((void**)&p_AR2, g_AR2);
    cudaGetSymbolAddress((void**)&p_Ah,  g_Ah);
    cudaGetSymbolAddress((void**)&p_Bh,  g_Bh);

    cudaFuncSetAttribute(gemm_mma,    cudaFuncAttributeMaxDynamicSharedMemorySize, GSMEM);
    cudaFuncSetAttribute(proj_ru_mma, cudaFuncAttributeMaxDynamicSharedMemorySize, PRU_SMEM);
    cudaFuncSetAttribute(proj_c_mma,  cudaFuncAttributeMaxDynamicSharedMemorySize, PC_SMEM);

    rowsum_kernel<<<NN, 256>>>(adj);                         // 1
    pack_permW<<<16384 + 288, 256>>>(inputs, hx, W_ru, W_c); // 2
    conv1<<<1024 + 4096, 256>>>(adj);                        // 3

    // 4: A1 = adjT @ XH   (profiled launch)
    gemm_mma<<<dim3(CXH / 256, 16), 512, GSMEM>>>(p_Ah, p_Bh, nullptr, p_A1, CXH, 1.0f, 0.0f);
    trans_f16<<<dim3(CXH / 64, 32), 256>>>(p_A1, p_Bh, CXH); // 5
    // 6: A2 = 2*adjT@A1 - XH
    gemm_mma<<<dim3(CXH / 256, 16), 512, GSMEM>>>(p_Ah, p_Bh, p_XH, p_A2, CXH, 2.0f, -1.0f);

    proj_ru_mma<<<NN / PN, 256, PRU_SMEM>>>(b_ru);           // 7 (emits RH, U, RH^T fp16)

    // 8: AR1 = adjT @ RH
    gemm_mma<<<dim3(C1 / 256, 16), 512, GSMEM>>>(p_Ah, p_Bh, nullptr, p_AR1, C1, 1.0f, 0.0f);
    trans_f16<<<dim3(C1 / 64, 32), 256>>>(p_AR1, p_Bh, C1);  // 9
    // 10: AR2 = 2*adjT@AR1 - RH
    gemm_mma<<<dim3(C1 / 256, 16), 512, GSMEM>>>(p_Ah, p_Bh, p_RH, p_AR2, C1, 2.0f, -1.0f);

    proj_c_mma<<<NN / PN, 256, PC_SMEM>>>(b_c, out);         // 11
}

// round 12
// speedup vs baseline: 1.5789x; 1.5789x over previous
#include <cuda_runtime.h>
#include <cuda_fp16.h>
#include <math.h>
#include <stdint.h>

#define NN 2048      // nodes
#define CXH 8192     // 2*64*64 columns of [x|h]
#define C1  4096     // 64*64
#define KD  2048     // GEMM K
#define FSTR 392     // padded half-stride for projection smem rows (384+8)
#define PN  8        // nodes per projection CTA

// ---------------- device scratch ----------------
__device__ float g_dinv[NN];
__device__ float g_XH [(size_t)NN * CXH];
__device__ float g_A1 [(size_t)NN * CXH];
__device__ float g_A2 [(size_t)NN * CXH];
__device__ float g_RH [(size_t)NN * C1];
__device__ float g_AR1[(size_t)NN * C1];
__device__ float g_AR2[(size_t)NN * C1];
__device__ float g_U  [(size_t)NN * C1];
__device__ __half g_Wruh[128 * 384];         // fp16, [n][k], k = s*64+f permuted
__device__ __half g_Wch [64 * 384];
__device__ __half g_Ah [(size_t)NN * KD];    // fp16 adjT, [m][k]
__device__ __half g_Bh [(size_t)CXH * KD];   // fp16 B operand #1 [c][k]
__device__ __half g_Bh2[(size_t)CXH * KD];   // fp16 B operand #2 (GEMM-fused transpose out)

// ---------------- helpers ----------------
__device__ __forceinline__ uint32_t smem_u32(const void* p) {
    uint32_t a;
    asm("{ .reg .u64 t; cvta.to.shared.u64 t, %1; cvt.u32.u64 %0, t; }" : "=r"(a) : "l"(p));
    return a;
}
__device__ __forceinline__ void cpasync16(uint32_t dst, const void* src) {
    asm volatile("cp.async.cg.shared.global [%0], [%1], 16;" :: "r"(dst), "l"(src));
}
__device__ __forceinline__ void ldsm4(uint32_t* r, uint32_t addr) {
    asm volatile("ldmatrix.sync.aligned.m8n8.x4.shared.b16 {%0,%1,%2,%3}, [%4];"
        : "=r"(r[0]), "=r"(r[1]), "=r"(r[2]), "=r"(r[3]) : "r"(addr));
}
__device__ __forceinline__ void mma16816(float* d, const uint32_t* a, const uint32_t* b) {
    asm volatile("mma.sync.aligned.m16n8k16.row.col.f32.f16.f16.f32 "
        "{%0,%1,%2,%3}, {%4,%5,%6,%7}, {%8,%9}, {%0,%1,%2,%3};"
        : "+f"(d[0]), "+f"(d[1]), "+f"(d[2]), "+f"(d[3])
        : "r"(a[0]), "r"(a[1]), "r"(a[2]), "r"(a[3]), "r"(b[0]), "r"(b[1]));
}
__device__ __forceinline__ int wsrc_row(int k) {
    int s = k >> 6, f = k & 63;
    return (s < 3) ? (f * 3 + s) : (192 + f * 3 + (s - 3));
}

// ---------------- launch 1: row sums ----------------
__global__ void rowsum_kernel(const float* __restrict__ adj) {
    int m = blockIdx.x;
    const float* row = adj + (size_t)m * NN;
    float s = 0.f;
    for (int i = threadIdx.x; i < NN; i += 256) s += row[i];
    #pragma unroll
    for (int o = 16; o; o >>= 1) s += __shfl_down_sync(0xffffffffu, s, o);
    __shared__ float sm[8];
    if ((threadIdx.x & 31) == 0) sm[threadIdx.x >> 5] = s;
    __syncthreads();
    if (threadIdx.x < 8) {
        float v = sm[threadIdx.x];
        #pragma unroll
        for (int o = 4; o; o >>= 1) v += __shfl_down_sync(0xffu, v, o);
        if (threadIdx.x == 0) g_dinv[m] = 1.0f / (v + 1.0f);
    }
}

// ---------------- launch 2: pack XH + build fp16 transposed weights ----------------
__global__ void pack_permW(const float* __restrict__ x, const float* __restrict__ h,
                           const float* __restrict__ Wru, const float* __restrict__ Wc) {
    int bid = blockIdx.x;
    int t = threadIdx.x;
    if (bid < 16384) {
        int idx4 = bid * 256 + t;
        int m = idx4 >> 11;
        int c = (idx4 & 2047) * 4;
        const float* src;
        if (c < C1) { int b = c >> 6, f = c & 63; src = x + (size_t)b * (NN * 64) + m * 64 + f; }
        else { int cc = c - C1; int b = cc >> 6, f = cc & 63; src = h + (size_t)b * (NN * 64) + m * 64 + f; }
        *(float4*)&g_XH[(size_t)m * CXH + c] = *(const float4*)src;
    } else {
        int idx = (bid - 16384) * 256 + t;
        if (idx < 128 * 384) {
            int n = idx / 384, k = idx % 384;
            g_Wruh[n * 384 + k] = __float2half_rn(Wru[wsrc_row(k) * 128 + n]);
        } else if (idx < 128 * 384 + 64 * 384) {
            int j = idx - 128 * 384;
            int n = j / 384, k = j % 384;
            g_Wch[n * 384 + k] = __float2half_rn(Wc[wsrc_row(k) * 64 + n]);
        }
    }
}

// ---------------- launch 3: build fp16 adjT + fp16 transpose of XH (fused) ----------------
__global__ void conv1(const float* __restrict__ adj) {
    __shared__ float tile[64][65];
    int bid = blockIdx.x;
    int t = threadIdx.x;
    if (bid < 1024) {
        __shared__ float sdinv[64];
        int k0 = (bid >> 5) * 64, m0 = (bid & 31) * 64;
        if (t < 64) sdinv[t] = g_dinv[k0 + t];
        #pragma unroll
        for (int i = 0; i < 16; i++) {
            int q = t + 256 * i; int r = q >> 6, c = q & 63;
            tile[r][c] = adj[(size_t)(k0 + r) * NN + m0 + c];
        }
        __syncthreads();
        #pragma unroll
        for (int i = 0; i < 16; i++) {
            int q = t + 256 * i; int f = q >> 6, n = q & 63;
            int kk = k0 + n, mm = m0 + f;
            float v = tile[n][f];
            if (kk == mm) v += 1.0f;
            g_Ah[(size_t)mm * KD + kk] = __float2half_rn(v * sdinv[n]);
        }
    } else {
        int tb = bid - 1024;                   // 4096 blocks
        int c0 = (tb & 127) * 64, k0 = (tb >> 7) * 64;
        #pragma unroll
        for (int i = 0; i < 16; i++) {
            int q = t + 256 * i; int r = q >> 6, c = q & 63;
            tile[r][c] = g_XH[(size_t)(k0 + r) * CXH + c0 + c];
        }
        __syncthreads();
        #pragma unroll
        for (int i = 0; i < 16; i++) {
            int q = t + 256 * i; int f = q >> 6, n = q & 63;
            g_Bh[(size_t)(c0 + f) * KD + (k0 + n)] = __float2half_rn(tile[n][f]);
        }
    }
}

// ---------------- HMMA GEMM: Cout = alpha*(A @ B^T) + beta*Cin [+ fp16 out^T] ----------------
// 512 threads, 16 warps, CTA tile 128x128, warp tile 32x32, BK=32, 4-stage.
// __launch_bounds__(512,2): 2 CTAs/SM (smem 80KB each) to overlap barrier/LDSM with MMA.
#define ROWB 80
#define TASZ (128 * ROWB)
#define STB  (2 * TASZ)           // 20480 B per stage
#define GSMEM (4 * STB)           // 81920 B
#define NST  (KD / 32)            // 64

__global__ __launch_bounds__(512, 2)
void gemm_mma(const __half* __restrict__ A, const __half* __restrict__ B,
              const float* __restrict__ Cin, float* __restrict__ Cout,
              __half* __restrict__ BhT,
              int Ncols, float alpha, float beta) {
    extern __shared__ char smem[];
    uint32_t sbase = smem_u32(smem);
    int t = threadIdx.x;
    int lane = t & 31, wid = t >> 5;
    int m0 = blockIdx.y * 128;
    int n0 = blockIdx.x * 128;
    int wm = (wid & 3) * 32;
    int wn = (wid >> 2) * 32;

    uint32_t aOff[2], bOff[2];
    #pragma unroll
    for (int mt = 0; mt < 2; mt++)
        aOff[mt] = (uint32_t)((wm + mt * 16 + (lane & 15)) * ROWB + (lane >> 4) * 16);
    #pragma unroll
    for (int np = 0; np < 2; np++)
        bOff[np] = (uint32_t)(TASZ + (wn + np * 16 + (lane & 7) + ((lane >> 4) << 3)) * ROWB
                              + ((lane >> 3) & 1) * 16);

    auto load_stage = [&](int s) {
        int slot = s & 3; int k0 = s * 32;
        uint32_t ab = sbase + slot * STB;
        const __half* gA = A + (size_t)m0 * KD + k0;
        const __half* gB = B + (size_t)n0 * KD + k0;
        {
            int r = t >> 2, c4 = t & 3;
            cpasync16(ab + r * ROWB + c4 * 16, gA + (size_t)r * KD + c4 * 8);
            cpasync16(ab + TASZ + r * ROWB + c4 * 16, gB + (size_t)r * KD + c4 * 8);
        }
        asm volatile("cp.async.commit_group;" ::: "memory");
    };

    float acc[2][4][4] = {};

    load_stage(0); load_stage(1); load_stage(2);

    for (int s = 0; s < NST; ++s) {
        if (s <= NST - 3)      asm volatile("cp.async.wait_group 2;" ::: "memory");
        else if (s == NST - 2) asm volatile("cp.async.wait_group 1;" ::: "memory");
        else                   asm volatile("cp.async.wait_group 0;" ::: "memory");
        __syncthreads();

        uint32_t sb = sbase + (s & 3) * STB;
        #pragma unroll
        for (int k16 = 0; k16 < 2; k16++) {
            uint32_t a[2][4], b[2][4];
            #pragma unroll
            for (int mt = 0; mt < 2; mt++) ldsm4(a[mt], sb + aOff[mt] + k16 * 32);
            #pragma unroll
            for (int np = 0; np < 2; np++) ldsm4(b[np], sb + bOff[np] + k16 * 32);
            #pragma unroll
            for (int mt = 0; mt < 2; mt++)
                #pragma unroll
                for (int nt = 0; nt < 4; nt++)
                    mma16816(acc[mt][nt], a[mt], &b[nt >> 1][(nt & 1) * 2]);
        }

        if (s + 3 < NST) load_stage(s + 3);
    }

    __syncthreads();   // pipeline smem dead; safe to reuse for transpose staging

    bool has_cin = (Cin != nullptr);
    bool has_bt  = (BhT != nullptr);
    __half* sT = (__half*)smem;          // [128][136] halfs (stride 272B = 17*16)
    #pragma unroll
    for (int mt = 0; mt < 2; mt++) {
        #pragma unroll
        for (int nt = 0; nt < 4; nt++) {
            int mr = wm + mt * 16 + (lane >> 2);
            int nr = wn + nt * 8 + (lane & 3) * 2;
            int m = m0 + mr, n = n0 + nr;
            size_t g0 = (size_t)m * Ncols + n;
            size_t g1 = g0 + (size_t)8 * Ncols;
            float v0 = alpha * acc[mt][nt][0], v1 = alpha * acc[mt][nt][1];
            float v2 = alpha * acc[mt][nt][2], v3 = alpha * acc[mt][nt][3];
            if (has_cin) {
                float2 c0 = *(const float2*)&Cin[g0];
                float2 c1 = *(const float2*)&Cin[g1];
                v0 += beta * c0.x; v1 += beta * c0.y;
                v2 += beta * c1.x; v3 += beta * c1.y;
            }
            float2 w0 = {v0, v1}, w1 = {v2, v3};
            *(float2*)&Cout[g0] = w0;
            *(float2*)&Cout[g1] = w1;
            if (has_bt) {
                sT[nr * 136 + mr]           = __float2half_rn(v0);
                sT[(nr + 1) * 136 + mr]     = __float2half_rn(v1);
                sT[nr * 136 + mr + 8]       = __float2half_rn(v2);
                sT[(nr + 1) * 136 + mr + 8] = __float2half_rn(v3);
            }
        }
    }
    if (has_bt) {
        __syncthreads();
        #pragma unroll
        for (int i = 0; i < 4; i++) {
            int idx = t + 512 * i;              // 2048 chunks of 16B
            int row = idx >> 4, c8 = idx & 15;
            uint4 v = *(uint4*)(sT + row * 136 + c8 * 8);
            *(uint4*)&BhT[(size_t)(n0 + row) * KD + m0 + c8 * 8] = v;
        }
    }
}

// ---------------- projection RU (multi-node): 8 nodes/CTA, 256 threads ----------------
#define WRU_B (128 * FSTR * 2)
#define FBUF_B (64 * FSTR * 2)
#define PRU_SMEM (WRU_B + 2 * FBUF_B)
__global__ __launch_bounds__(256)
void proj_ru_mma(const float* __restrict__ b_ru) {
    extern __shared__ char ps[];
    __half* Ws = (__half*)ps;                          // [128][FSTR]
    __half* F0 = (__half*)(ps + WRU_B);                // [64][FSTR] x2
    uint32_t wsb = smem_u32(Ws), fsb = smem_u32(F0);
    int t = threadIdx.x;
    int lane = t & 31, wid = t >> 5;
    int m0 = blockIdx.x * PN;
    int wm = (wid & 1) * 32, wn = (wid >> 1) * 32;

    #pragma unroll
    for (int j = 0; j < 24; j++) {
        int q = j * 256 + t;
        int n = q / 48, c = q % 48;
        *(uint4*)(Ws + n * FSTR + c * 8) = *(const uint4*)(g_Wruh + n * 384 + c * 8);
    }

    float4 r[24];
    auto ldF = [&](int m) {
        const float* segp[6] = {
            g_XH + (size_t)m * CXH,      g_A1 + (size_t)m * CXH,      g_A2 + (size_t)m * CXH,
            g_XH + (size_t)m * CXH + C1, g_A1 + (size_t)m * CXH + C1, g_A2 + (size_t)m * CXH + C1 };
        #pragma unroll
        for (int j = 0; j < 24; j++) {
            int q = j * 256 + t;
            int bb = q / 96, f4 = q % 96;
            int col = f4 * 4, s = col >> 6, f = col & 63;
            r[j] = *(const float4*)(segp[s] + bb * 64 + f);
        }
    };
    auto stF = [&](__half* buf) {
        #pragma unroll
        for (int j = 0; j < 24; j++) {
            int q = j * 256 + t;
            int bb = q / 96, col = (q % 96) * 4;
            __half2* d = (__half2*)(buf + bb * FSTR + col);
            d[0] = __floats2half2_rn(r[j].x, r[j].y);
            d[1] = __floats2half2_rn(r[j].z, r[j].w);
        }
    };

    uint32_t aRel[2], bOff[2];
    #pragma unroll
    for (int mt = 0; mt < 2; mt++)
        aRel[mt] = (wm + mt * 16 + (lane & 15)) * (FSTR * 2) + (lane >> 4) * 16;
    #pragma unroll
    for (int np = 0; np < 2; np++)
        bOff[np] = wsb + (wn + np * 16 + (lane & 7) + ((lane >> 4) << 3)) * (FSTR * 2)
                   + ((lane >> 3) & 1) * 16;

    ldF(m0);
    stF(F0);
    __syncthreads();

    for (int i = 0; i < PN; i++) {
        int m = m0 + i;
        if (i + 1 < PN) ldF(m + 1);

        uint32_t fb = fsb + (i & 1) * FBUF_B;
        float acc[2][4][4] = {};
        #pragma unroll
        for (int k = 0; k < 24; k++) {
            uint32_t a[2][4], b[2][4];
            ldsm4(a[0], fb + aRel[0] + k * 32);
            ldsm4(a[1], fb + aRel[1] + k * 32);
            ldsm4(b[0], bOff[0] + k * 32);
            ldsm4(b[1], bOff[1] + k * 32);
            #pragma unroll
            for (int mt = 0; mt < 2; mt++)
                #pragma unroll
                for (int nt = 0; nt < 4; nt++)
                    mma16816(acc[mt][nt], a[mt], &b[nt >> 1][(nt & 1) * 2]);
        }

        #pragma unroll
        for (int mt = 0; mt < 2; mt++) {
            #pragma unroll
            for (int nt = 0; nt < 4; nt++) {
                int brow = wm + mt * 16 + (lane >> 2);
                int o = wn + nt * 8 + (lane & 3) * 2;
                float bo0 = b_ru[o], bo1 = b_ru[o + 1];
                #pragma unroll
                for (int hi = 0; hi < 2; hi++) {
                    int bb = brow + hi * 8;
                    float v0 = 1.0f / (1.0f + expf(-(acc[mt][nt][hi * 2 + 0] + bo0)));
                    float v1 = 1.0f / (1.0f + expf(-(acc[mt][nt][hi * 2 + 1] + bo1)));
                    if (o < 64) {
                        float h0 = g_XH[(size_t)m * CXH + C1 + bb * 64 + o];
                        float h1 = g_XH[(size_t)m * CXH + C1 + bb * 64 + o + 1];
                        float rh0 = v0 * h0, rh1 = v1 * h1;
                        g_RH[(size_t)m * C1 + bb * 64 + o]     = rh0;
                        g_RH[(size_t)m * C1 + bb * 64 + o + 1] = rh1;
                        g_Bh[(size_t)(bb * 64 + o) * KD + m]     = __float2half_rn(rh0);
                        g_Bh[(size_t)(bb * 64 + o + 1) * KD + m] = __float2half_rn(rh1);
                    } else {
                        g_U[(size_t)m * C1 + bb * 64 + (o - 64)]     = v0;
                        g_U[(size_t)m * C1 + bb * 64 + (o - 64) + 1] = v1;
                    }
                }
            }
        }

        if (i + 1 < PN) stF((__half*)(ps + WRU_B + ((i + 1) & 1) * FBUF_B));
        __syncthreads();
    }
}

// ---------------- projection C + GRU combine (multi-node): 8 nodes/CTA ----------------
#define WC_B (64 * FSTR * 2)
#define PC_SMEM (WC_B + 2 * FBUF_B)
__global__ __launch_bounds__(256)
void proj_c_mma(const float* __restrict__ b_c, float* __restrict__ out) {
    extern __shared__ char ps[];
    __half* Ws = (__half*)ps;
    __half* F0 = (__half*)(ps + WC_B);
    uint32_t wsb = smem_u32(Ws), fsb = smem_u32(F0);
    int t = threadIdx.x;
    int lane = t & 31, wid = t >> 5;
    int m0 = blockIdx.x * PN;
    int wm = (wid & 1) * 32, wn = (wid >> 1) * 16;

    #pragma unroll
    for (int j = 0; j < 12; j++) {
        int q = j * 256 + t;
        int n = q / 48, c = q % 48;
        *(uint4*)(Ws + n * FSTR + c * 8) = *(const uint4*)(g_Wch + n * 384 + c * 8);
    }

    float4 r[24];
    auto ldF = [&](int m) {
        const float* segp[6] = {
            g_XH + (size_t)m * CXH, g_A1 + (size_t)m * CXH, g_A2 + (size_t)m * CXH,
            g_RH + (size_t)m * C1,  g_AR1 + (size_t)m * C1, g_AR2 + (size_t)m * C1 };
        #pragma unroll
        for (int j = 0; j < 24; j++) {
            int q = j * 256 + t;
            int bb = q / 96, f4 = q % 96;
            int col = f4 * 4, s = col >> 6, f = col & 63;
            r[j] = *(const float4*)(segp[s] + bb * 64 + f);
        }
    };
    auto stF = [&](__half* buf) {
        #pragma unroll
        for (int j = 0; j < 24; j++) {
            int q = j * 256 + t;
            int bb = q / 96, col = (q % 96) * 4;
            __half2* d = (__half2*)(buf + bb * FSTR + col);
            d[0] = __floats2half2_rn(r[j].x, r[j].y);
            d[1] = __floats2half2_rn(r[j].z, r[j].w);
        }
    };

    uint32_t aRel[2], bOff;
    #pragma unroll
    for (int mt = 0; mt < 2; mt++)
        aRel[mt] = (wm + mt * 16 + (lane & 15)) * (FSTR * 2) + (lane >> 4) * 16;
    bOff = wsb + (wn + (lane & 7) + ((lane >> 4) << 3)) * (FSTR * 2)
           + ((lane >> 3) & 1) * 16;

    ldF(m0);
    stF(F0);
    __syncthreads();

    for (int i = 0; i < PN; i++) {
        int m = m0 + i;
        if (i + 1 < PN) ldF(m + 1);

        uint32_t fb = fsb + (i & 1) * FBUF_B;
        float acc[2][2][4] = {};
        #pragma unroll
        for (int k = 0; k < 24; k++) {
            uint32_t a[2][4], b[4];
            ldsm4(a[0], fb + aRel[0] + k * 32);
            ldsm4(a[1], fb + aRel[1] + k * 32);
            ldsm4(b, bOff + k * 32);
            #pragma unroll
            for (int mt = 0; mt < 2; mt++)
                #pragma unroll
                for (int nt = 0; nt < 2; nt++)
                    mma16816(acc[mt][nt], a[mt], &b[nt * 2]);
        }

        #pragma unroll
        for (int mt = 0; mt < 2; mt++) {
            #pragma unroll
            for (int nt = 0; nt < 2; nt++) {
                int brow = wm + mt * 16 + (lane >> 2);
                int o = wn + nt * 8 + (lane & 3) * 2;
                float bo0 = b_c[o], bo1 = b_c[o + 1];
                #pragma unroll
                for (int hi = 0; hi < 2; hi++) {
                    int bb = brow + hi * 8;
                    float c0 = tanhf(acc[mt][nt][hi * 2 + 0] + bo0);
                    float c1 = tanhf(acc[mt][nt][hi * 2 + 1] + bo1);
                    float u0 = g_U[(size_t)m * C1 + bb * 64 + o];
                    float u1 = g_U[(size_t)m * C1 + bb * 64 + o + 1];
                    float h0 = g_XH[(size_t)m * CXH + C1 + bb * 64 + o];
                    float h1 = g_XH[(size_t)m * CXH + C1 + bb * 64 + o + 1];
                    float2 ov = {u0 * h0 + (1.0f - u0) * c0, u1 * h1 + (1.0f - u1) * c1};
                    *(float2*)&out[(size_t)bb * (NN * 64) + m * 64 + o] = ov;
                }
            }
        }

        if (i + 1 < PN) stF((__half*)(ps + WC_B + ((i + 1) & 1) * FBUF_B));
        __syncthreads();
    }
}

// ---------------- launch ----------------
extern "C" void kernel_launch(void* const* d_in, const int* in_sizes, int n_in,
                              void* d_out, int out_size) {
    const float* inputs = (const float*)d_in[0];
    const float* hx     = (const float*)d_in[1];
    const float* adj    = (const float*)d_in[2];
    const float* W_ru   = (const float*)d_in[3];
    const float* b_ru   = (const float*)d_in[4];
    const float* W_c    = (const float*)d_in[5];
    const float* b_c    = (const float*)d_in[6];
    float* out = (float*)d_out;

    float *p_XH, *p_A1, *p_A2, *p_RH, *p_AR1, *p_AR2;
    __half *p_Ah, *p_Bh, *p_Bh2;
    cudaGetSymbolAddress((void**)&p_XH,  g_XH);
    cudaGetSymbolAddress((void**)&p_A1,  g_A1);
    cudaGetSymbolAddress((void**)&p_A2,  g_A2);
    cudaGetSymbolAddress((void**)&p_RH,  g_RH);
    cudaGetSymbolAddress((void**)&p_AR1, g_AR1);
    cudaGetSymbolAddress((void**)&p_AR2, g_AR2);
    cudaGetSymbolAddress((void**)&p_Ah,  g_Ah);
    cudaGetSymbolAddress((void**)&p_Bh,  g_Bh);
    cudaGetSymbolAddress((void**)&p_Bh2, g_Bh2);

    cudaFuncSetAttribute(gemm_mma,    cudaFuncAttributeMaxDynamicSharedMemorySize, GSMEM);
    cudaFuncSetAttribute(proj_ru_mma, cudaFuncAttributeMaxDynamicSharedMemorySize, PRU_SMEM);
    cudaFuncSetAttribute(proj_c_mma,  cudaFuncAttributeMaxDynamicSharedMemorySize, PC_SMEM);

    rowsum_kernel<<<NN, 256>>>(adj);                         // 1
    pack_permW<<<16384 + 288, 256>>>(inputs, hx, W_ru, W_c); // 2
    conv1<<<1024 + 4096, 256>>>(adj);                        // 3

    // 4: A1 = adjT @ XH  (+ fused fp16 A1^T into g_Bh2)   (profiled launch)
    gemm_mma<<<dim3(CXH / 128, 16), 512, GSMEM>>>(p_Ah, p_Bh, nullptr, p_A1, p_Bh2, CXH, 1.0f, 0.0f);
    // 5: A2 = 2*adjT@A1 - XH
    gemm_mma<<<dim3(CXH / 128, 16), 512, GSMEM>>>(p_Ah, p_Bh2, p_XH, p_A2, nullptr, CXH, 2.0f, -1.0f);

    proj_ru_mma<<<NN / PN, 256, PRU_SMEM>>>(b_ru);           // 6 (emits RH, U, RH^T fp16 into g_Bh)

    // 7: AR1 = adjT @ RH  (+ fused fp16 AR1^T into g_Bh2)
    gemm_mma<<<dim3(C1 / 128, 16), 512, GSMEM>>>(p_Ah, p_Bh, nullptr, p_AR1, p_Bh2, C1, 1.0f, 0.0f);
    // 8: AR2 = 2*adjT@AR1 - RH
    gemm_mma<<<dim3(C1 / 128, 16), 512, GSMEM>>>(p_Ah, p_Bh2, p_RH, p_AR2, nullptr, C1, 2.0f, -1.0f);

    proj_c_mma<<<NN / PN, 256, PC_SMEM>>>(b_c, out);         // 9
}

// round 17
// speedup vs baseline: 1.6185x; 1.0251x over previous
#include <cuda_runtime.h>
#include <cuda_fp16.h>
#include <math.h>
#include <stdint.h>

#define NN 2048      // nodes
#define CXH 8192     // 2*64*64 columns of [x|h]
#define C1  4096     // 64*64
#define KD  2048     // GEMM K
#define FSTR 392     // padded half-stride for projection smem rows (384+8)
#define PN  8        // nodes per projection CTA

// ---------------- device scratch ----------------
__device__ float g_dinv[NN];
__device__ float g_XH [(size_t)NN * CXH];    // fp32 (beta-add + GRU pointwise)
__device__ float g_RH [(size_t)NN * C1];     // fp32 (beta-add)
__device__ float g_U  [(size_t)NN * C1];
__device__ __half g_XHh [(size_t)NN * CXH];  // fp16 proj feature copies
__device__ __half g_A1h [(size_t)NN * CXH];
__device__ __half g_A2h [(size_t)NN * CXH];
__device__ __half g_RHh [(size_t)NN * C1];
__device__ __half g_AR1h[(size_t)NN * C1];
__device__ __half g_AR2h[(size_t)NN * C1];
__device__ __half g_Wruh[128 * 384];         // fp16, [n][k], k = s*64+f permuted
__device__ __half g_Wch [64 * 384];
__device__ __half g_Ah [(size_t)NN * KD];    // fp16 adjT, [m][k]
__device__ __half g_Bh [(size_t)CXH * KD];   // fp16 B operand #1 [c][k]
__device__ __half g_Bh2[(size_t)CXH * KD];   // fp16 B operand #2 (GEMM-fused transpose out)

// ---------------- helpers ----------------
__device__ __forceinline__ uint32_t smem_u32(const void* p) {
    uint32_t a;
    asm("{ .reg .u64 t; cvta.to.shared.u64 t, %1; cvt.u32.u64 %0, t; }" : "=r"(a) : "l"(p));
    return a;
}
__device__ __forceinline__ void cpasync16(uint32_t dst, const void* src) {
    asm volatile("cp.async.cg.shared.global [%0], [%1], 16;" :: "r"(dst), "l"(src));
}
__device__ __forceinline__ void ldsm4(uint32_t* r, uint32_t addr) {
    asm volatile("ldmatrix.sync.aligned.m8n8.x4.shared.b16 {%0,%1,%2,%3}, [%4];"
        : "=r"(r[0]), "=r"(r[1]), "=r"(r[2]), "=r"(r[3]) : "r"(addr));
}
__device__ __forceinline__ void mma16816(float* d, const uint32_t* a, const uint32_t* b) {
    asm volatile("mma.sync.aligned.m16n8k16.row.col.f32.f16.f16.f32 "
        "{%0,%1,%2,%3}, {%4,%5,%6,%7}, {%8,%9}, {%0,%1,%2,%3};"
        : "+f"(d[0]), "+f"(d[1]), "+f"(d[2]), "+f"(d[3])
        : "r"(a[0]), "r"(a[1]), "r"(a[2]), "r"(a[3]), "r"(b[0]), "r"(b[1]));
}
__device__ __forceinline__ int wsrc_row(int k) {
    int s = k >> 6, f = k & 63;
    return (s < 3) ? (f * 3 + s) : (192 + f * 3 + (s - 3));
}

// ---------------- launch 1: row sums ----------------
__global__ void rowsum_kernel(const float* __restrict__ adj) {
    int m = blockIdx.x;
    const float* row = adj + (size_t)m * NN;
    float s = 0.f;
    for (int i = threadIdx.x; i < NN; i += 256) s += row[i];
    #pragma unroll
    for (int o = 16; o; o >>= 1) s += __shfl_down_sync(0xffffffffu, s, o);
    __shared__ float sm[8];
    if ((threadIdx.x & 31) == 0) sm[threadIdx.x >> 5] = s;
    __syncthreads();
    if (threadIdx.x < 8) {
        float v = sm[threadIdx.x];
        #pragma unroll
        for (int o = 4; o; o >>= 1) v += __shfl_down_sync(0xffu, v, o);
        if (threadIdx.x == 0) g_dinv[m] = 1.0f / (v + 1.0f);
    }
}

// ---------------- launch 2: pack XH (fp32 + fp16) + build fp16 transposed weights ----------------
__global__ void pack_permW(const float* __restrict__ x, const float* __restrict__ h,
                           const float* __restrict__ Wru, const float* __restrict__ Wc) {
    int bid = blockIdx.x;
    int t = threadIdx.x;
    if (bid < 16384) {
        int idx4 = bid * 256 + t;
        int m = idx4 >> 11;
        int c = (idx4 & 2047) * 4;
        const float* src;
        if (c < C1) { int b = c >> 6, f = c & 63; src = x + (size_t)b * (NN * 64) + m * 64 + f; }
        else { int cc = c - C1; int b = cc >> 6, f = cc & 63; src = h + (size_t)b * (NN * 64) + m * 64 + f; }
        float4 v = *(const float4*)src;
        *(float4*)&g_XH[(size_t)m * CXH + c] = v;
        __half2* hd = (__half2*)&g_XHh[(size_t)m * CXH + c];
        hd[0] = __floats2half2_rn(v.x, v.y);
        hd[1] = __floats2half2_rn(v.z, v.w);
    } else {
        int idx = (bid - 16384) * 256 + t;
        if (idx < 128 * 384) {
            int n = idx / 384, k = idx % 384;
            g_Wruh[n * 384 + k] = __float2half_rn(Wru[wsrc_row(k) * 128 + n]);
        } else if (idx < 128 * 384 + 64 * 384) {
            int j = idx - 128 * 384;
            int n = j / 384, k = j % 384;
            g_Wch[n * 384 + k] = __float2half_rn(Wc[wsrc_row(k) * 64 + n]);
        }
    }
}

// ---------------- launch 3: build fp16 adjT + fp16 transpose of XH (fused) ----------------
__global__ void conv1(const float* __restrict__ adj) {
    __shared__ float tile[64][65];
    int bid = blockIdx.x;
    int t = threadIdx.x;
    if (bid < 1024) {
        __shared__ float sdinv[64];
        int k0 = (bid >> 5) * 64, m0 = (bid & 31) * 64;
        if (t < 64) sdinv[t] = g_dinv[k0 + t];
        #pragma unroll
        for (int i = 0; i < 16; i++) {
            int q = t + 256 * i; int r = q >> 6, c = q & 63;
            tile[r][c] = adj[(size_t)(k0 + r) * NN + m0 + c];
        }
        __syncthreads();
        #pragma unroll
        for (int i = 0; i < 16; i++) {
            int q = t + 256 * i; int f = q >> 6, n = q & 63;
            int kk = k0 + n, mm = m0 + f;
            float v = tile[n][f];
            if (kk == mm) v += 1.0f;
            g_Ah[(size_t)mm * KD + kk] = __float2half_rn(v * sdinv[n]);
        }
    } else {
        int tb = bid - 1024;                   // 4096 blocks
        int c0 = (tb & 127) * 64, k0 = (tb >> 7) * 64;
        #pragma unroll
        for (int i = 0; i < 16; i++) {
            int q = t + 256 * i; int r = q >> 6, c = q & 63;
            tile[r][c] = g_XH[(size_t)(k0 + r) * CXH + c0 + c];
        }
        __syncthreads();
        #pragma unroll
        for (int i = 0; i < 16; i++) {
            int q = t + 256 * i; int f = q >> 6, n = q & 63;
            g_Bh[(size_t)(c0 + f) * KD + (k0 + n)] = __float2half_rn(tile[n][f]);
        }
    }
}

// ---------------- HMMA GEMM: Cout(fp16) = alpha*(A @ B^T) + beta*Cin [+ fp16 out^T] ----------------
// 512 threads, 16 warps, CTA tile 128x128, warp tile 32x32, BK=32, 4-stage, 2 CTAs/SM.
#define ROWB 80
#define TASZ (128 * ROWB)
#define STB  (2 * TASZ)           // 20480 B per stage
#define GSMEM (4 * STB)           // 81920 B
#define NST  (KD / 32)            // 64

__global__ __launch_bounds__(512, 2)
void gemm_mma(const __half* __restrict__ A, const __half* __restrict__ B,
              const float* __restrict__ Cin, __half* __restrict__ Cout,
              __half* __restrict__ BhT,
              int Ncols, float alpha, float beta) {
    extern __shared__ char smem[];
    uint32_t sbase = smem_u32(smem);
    int t = threadIdx.x;
    int lane = t & 31, wid = t >> 5;
    int m0 = blockIdx.y * 128;
    int n0 = blockIdx.x * 128;
    int wm = (wid & 3) * 32;
    int wn = (wid >> 2) * 32;

    uint32_t aOff[2], bOff[2];
    #pragma unroll
    for (int mt = 0; mt < 2; mt++)
        aOff[mt] = (uint32_t)((wm + mt * 16 + (lane & 15)) * ROWB + (lane >> 4) * 16);
    #pragma unroll
    for (int np = 0; np < 2; np++)
        bOff[np] = (uint32_t)(TASZ + (wn + np * 16 + (lane & 7) + ((lane >> 4) << 3)) * ROWB
                              + ((lane >> 3) & 1) * 16);

    auto load_stage = [&](int s) {
        int slot = s & 3; int k0 = s * 32;
        uint32_t ab = sbase + slot * STB;
        const __half* gA = A + (size_t)m0 * KD + k0;
        const __half* gB = B + (size_t)n0 * KD + k0;
        {
            int r = t >> 2, c4 = t & 3;
            cpasync16(ab + r * ROWB + c4 * 16, gA + (size_t)r * KD + c4 * 8);
            cpasync16(ab + TASZ + r * ROWB + c4 * 16, gB + (size_t)r * KD + c4 * 8);
        }
        asm volatile("cp.async.commit_group;" ::: "memory");
    };

    float acc[2][4][4] = {};

    load_stage(0); load_stage(1); load_stage(2);

    for (int s = 0; s < NST; ++s) {
        if (s <= NST - 3)      asm volatile("cp.async.wait_group 2;" ::: "memory");
        else if (s == NST - 2) asm volatile("cp.async.wait_group 1;" ::: "memory");
        else                   asm volatile("cp.async.wait_group 0;" ::: "memory");
        __syncthreads();

        uint32_t sb = sbase + (s & 3) * STB;
        #pragma unroll
        for (int k16 = 0; k16 < 2; k16++) {
            uint32_t a[2][4], b[2][4];
            #pragma unroll
            for (int mt = 0; mt < 2; mt++) ldsm4(a[mt], sb + aOff[mt] + k16 * 32);
            #pragma unroll
            for (int np = 0; np < 2; np++) ldsm4(b[np], sb + bOff[np] + k16 * 32);
            #pragma unroll
            for (int mt = 0; mt < 2; mt++)
                #pragma unroll
                for (int nt = 0; nt < 4; nt++)
                    mma16816(acc[mt][nt], a[mt], &b[nt >> 1][(nt & 1) * 2]);
        }

        if (s + 3 < NST) load_stage(s + 3);
    }

    __syncthreads();   // pipeline smem dead; safe to reuse for transpose staging

    bool has_cin = (Cin != nullptr);
    bool has_bt  = (BhT != nullptr);
    __half* sT = (__half*)smem;          // [128][136] halfs
    #pragma unroll
    for (int mt = 0; mt < 2; mt++) {
        #pragma unroll
        for (int nt = 0; nt < 4; nt++) {
            int mr = wm + mt * 16 + (lane >> 2);
            int nr = wn + nt * 8 + (lane & 3) * 2;
            int m = m0 + mr, n = n0 + nr;
            size_t g0 = (size_t)m * Ncols + n;
            size_t g1 = g0 + (size_t)8 * Ncols;
            float v0 = alpha * acc[mt][nt][0], v1 = alpha * acc[mt][nt][1];
            float v2 = alpha * acc[mt][nt][2], v3 = alpha * acc[mt][nt][3];
            if (has_cin) {
                float2 c0 = *(const float2*)&Cin[g0];
                float2 c1 = *(const float2*)&Cin[g1];
                v0 += beta * c0.x; v1 += beta * c0.y;
                v2 += beta * c1.x; v3 += beta * c1.y;
            }
            __half2 h01 = __floats2half2_rn(v0, v1);
            __half2 h23 = __floats2half2_rn(v2, v3);
            *(__half2*)&Cout[g0] = h01;
            *(__half2*)&Cout[g1] = h23;
            if (has_bt) {
                sT[nr * 136 + mr]           = __low2half(h01);
                sT[(nr + 1) * 136 + mr]     = __high2half(h01);
                sT[nr * 136 + mr + 8]       = __low2half(h23);
                sT[(nr + 1) * 136 + mr + 8] = __high2half(h23);
            }
        }
    }
    if (has_bt) {
        __syncthreads();
        #pragma unroll
        for (int i = 0; i < 4; i++) {
            int idx = t + 512 * i;              // 2048 chunks of 16B
            int row = idx >> 4, c8 = idx & 15;
            uint4 v = *(uint4*)(sT + row * 136 + c8 * 8);
            *(uint4*)&BhT[(size_t)(n0 + row) * KD + m0 + c8 * 8] = v;
        }
    }
}

// ---------------- projection RU (multi-node, fp16 cp.async loader) ----------------
#define WRU_B (128 * FSTR * 2)
#define FBUF_B (64 * FSTR * 2)
#define PRU_SMEM (WRU_B + 2 * FBUF_B)
__global__ __launch_bounds__(256)
void proj_ru_mma(const float* __restrict__ b_ru) {
    extern __shared__ char ps[];
    __half* Ws = (__half*)ps;                          // [128][FSTR]
    uint32_t wsb = smem_u32(Ws);
    uint32_t fsb = wsb + WRU_B;
    int t = threadIdx.x;
    int lane = t & 31, wid = t >> 5;
    int m0 = blockIdx.x * PN;
    int wm = (wid & 1) * 32, wn = (wid >> 1) * 32;

    #pragma unroll
    for (int j = 0; j < 24; j++) {
        int q = j * 256 + t;
        int n = q / 48, c = q % 48;
        *(uint4*)(Ws + n * FSTR + c * 8) = *(const uint4*)(g_Wruh + n * 384 + c * 8);
    }

    // fp16 feature loader: 6 segs x 64 rows x 8 chunks(16B) = 3072 chunks/node
    auto load_node = [&](int i) {
        int m = m0 + i;
        uint32_t fb = fsb + (i & 1) * FBUF_B;
        const __half* segp[6] = {
            g_XHh + (size_t)m * CXH,      g_A1h + (size_t)m * CXH,      g_A2h + (size_t)m * CXH,
            g_XHh + (size_t)m * CXH + C1, g_A1h + (size_t)m * CXH + C1, g_A2h + (size_t)m * CXH + C1 };
        #pragma unroll
        for (int j = 0; j < 12; j++) {
            int q = j * 256 + t;
            int s = q >> 9, r = q & 511;
            int bb = r >> 3, ch = r & 7;
            cpasync16(fb + bb * (FSTR * 2) + s * 128 + ch * 16, segp[s] + bb * 64 + ch * 8);
        }
        asm volatile("cp.async.commit_group;" ::: "memory");
    };

    uint32_t aRel[2], bOff[2];
    #pragma unroll
    for (int mt = 0; mt < 2; mt++)
        aRel[mt] = (wm + mt * 16 + (lane & 15)) * (FSTR * 2) + (lane >> 4) * 16;
    #pragma unroll
    for (int np = 0; np < 2; np++)
        bOff[np] = wsb + (wn + np * 16 + (lane & 7) + ((lane >> 4) << 3)) * (FSTR * 2)
                   + ((lane >> 3) & 1) * 16;

    load_node(0);

    for (int i = 0; i < PN; i++) {
        int m = m0 + i;
        if (i + 1 < PN) {
            load_node(i + 1);
            asm volatile("cp.async.wait_group 1;" ::: "memory");
        } else {
            asm volatile("cp.async.wait_group 0;" ::: "memory");
        }
        __syncthreads();

        uint32_t fb = fsb + (i & 1) * FBUF_B;
        float acc[2][4][4] = {};
        #pragma unroll
        for (int k = 0; k < 24; k++) {
            uint32_t a[2][4], b[2][4];
            ldsm4(a[0], fb + aRel[0] + k * 32);
            ldsm4(a[1], fb + aRel[1] + k * 32);
            ldsm4(b[0], bOff[0] + k * 32);
            ldsm4(b[1], bOff[1] + k * 32);
            #pragma unroll
            for (int mt = 0; mt < 2; mt++)
                #pragma unroll
                for (int nt = 0; nt < 4; nt++)
                    mma16816(acc[mt][nt], a[mt], &b[nt >> 1][(nt & 1) * 2]);
        }

        #pragma unroll
        for (int mt = 0; mt < 2; mt++) {
            #pragma unroll
            for (int nt = 0; nt < 4; nt++) {
                int brow = wm + mt * 16 + (lane >> 2);
                int o = wn + nt * 8 + (lane & 3) * 2;
                float bo0 = b_ru[o], bo1 = b_ru[o + 1];
                #pragma unroll
                for (int hi = 0; hi < 2; hi++) {
                    int bb = brow + hi * 8;
                    float v0 = 1.0f / (1.0f + expf(-(acc[mt][nt][hi * 2 + 0] + bo0)));
                    float v1 = 1.0f / (1.0f + expf(-(acc[mt][nt][hi * 2 + 1] + bo1)));
                    if (o < 64) {
                        float h0 = g_XH[(size_t)m * CXH + C1 + bb * 64 + o];
                        float h1 = g_XH[(size_t)m * CXH + C1 + bb * 64 + o + 1];
                        float rh0 = v0 * h0, rh1 = v1 * h1;
                        g_RH[(size_t)m * C1 + bb * 64 + o]     = rh0;
                        g_RH[(size_t)m * C1 + bb * 64 + o + 1] = rh1;
                        __half hh0 = __float2half_rn(rh0), hh1 = __float2half_rn(rh1);
                        *(__half2*)&g_RHh[(size_t)m * C1 + bb * 64 + o] = __halves2half2(hh0, hh1);
                        g_Bh[(size_t)(bb * 64 + o) * KD + m]     = hh0;
                        g_Bh[(size_t)(bb * 64 + o + 1) * KD + m] = hh1;
                    } else {
                        g_U[(size_t)m * C1 + bb * 64 + (o - 64)]     = v0;
                        g_U[(size_t)m * C1 + bb * 64 + (o - 64) + 1] = v1;
                    }
                }
            }
        }
        __syncthreads();
    }
}

// ---------------- projection C + GRU combine (multi-node, fp16 cp.async loader) ----------------
#define WC_B (64 * FSTR * 2)
#define PC_SMEM (WC_B + 2 * FBUF_B)
__global__ __launch_bounds__(256)
void proj_c_mma(const float* __restrict__ b_c, float* __restrict__ out) {
    extern __shared__ char ps[];
    __half* Ws = (__half*)ps;
    uint32_t wsb = smem_u32(Ws);
    uint32_t fsb = wsb + WC_B;
    int t = threadIdx.x;
    int lane = t & 31, wid = t >> 5;
    int m0 = blockIdx.x * PN;
    int wm = (wid & 1) * 32, wn = (wid >> 1) * 16;

    #pragma unroll
    for (int j = 0; j < 12; j++) {
        int q = j * 256 + t;
        int n = q / 48, c = q % 48;
        *(uint4*)(Ws + n * FSTR + c * 8) = *(const uint4*)(g_Wch + n * 384 + c * 8);
    }

    auto load_node = [&](int i) {
        int m = m0 + i;
        uint32_t fb = fsb + (i & 1) * FBUF_B;
        const __half* segp[6] = {
            g_XHh + (size_t)m * CXH, g_A1h + (size_t)m * CXH, g_A2h + (size_t)m * CXH,
            g_RHh + (size_t)m * C1,  g_AR1h + (size_t)m * C1, g_AR2h + (size_t)m * C1 };
        #pragma unroll
        for (int j = 0; j < 12; j++) {
            int q = j * 256 + t;
            int s = q >> 9, r = q & 511;
            int bb = r >> 3, ch = r & 7;
            cpasync16(fb + bb * (FSTR * 2) + s * 128 + ch * 16, segp[s] + bb * 64 + ch * 8);
        }
        asm volatile("cp.async.commit_group;" ::: "memory");
    };

    uint32_t aRel[2], bOff;
    #pragma unroll
    for (int mt = 0; mt < 2; mt++)
        aRel[mt] = (wm + mt * 16 + (lane & 15)) * (FSTR * 2) + (lane >> 4) * 16;
    bOff = wsb + (wn + (lane & 7) + ((lane >> 4) << 3)) * (FSTR * 2)
           + ((lane >> 3) & 1) * 16;

    load_node(0);

    for (int i = 0; i < PN; i++) {
        int m = m0 + i;
        if (i + 1 < PN) {
            load_node(i + 1);
            asm volatile("cp.async.wait_group 1;" ::: "memory");
        } else {
            asm volatile("cp.async.wait_group 0;" ::: "memory");
        }
        __syncthreads();

        uint32_t fb = fsb + (i & 1) * FBUF_B;
        float acc[2][2][4] = {};
        #pragma unroll
        for (int k = 0; k < 24; k++) {
            uint32_t a[2][4], b[4];
            ldsm4(a[0], fb + aRel[0] + k * 32);
            ldsm4(a[1], fb + aRel[1] + k * 32);
            ldsm4(b, bOff + k * 32);
            #pragma unroll
            for (int mt = 0; mt < 2; mt++)
                #pragma unroll
                for (int nt = 0; nt < 2; nt++)
                    mma16816(acc[mt][nt], a[mt], &b[nt * 2]);
        }

        #pragma unroll
        for (int mt = 0; mt < 2; mt++) {
            #pragma unroll
            for (int nt = 0; nt < 2; nt++) {
                int brow = wm + mt * 16 + (lane >> 2);
                int o = wn + nt * 8 + (lane & 3) * 2;
                float bo0 = b_c[o], bo1 = b_c[o + 1];
                #pragma unroll
                for (int hi = 0; hi < 2; hi++) {
                    int bb = brow + hi * 8;
                    float c0 = tanhf(acc[mt][nt][hi * 2 + 0] + bo0);
                    float c1 = tanhf(acc[mt][nt][hi * 2 + 1] + bo1);
                    float u0 = g_U[(size_t)m * C1 + bb * 64 + o];
                    float u1 = g_U[(size_t)m * C1 + bb * 64 + o + 1];
                    float h0 = g_XH[(size_t)m * CXH + C1 + bb * 64 + o];
                    float h1 = g_XH[(size_t)m * CXH + C1 + bb * 64 + o + 1];
                    float2 ov = {u0 * h0 + (1.0f - u0) * c0, u1 * h1 + (1.0f - u1) * c1};
                    *(float2*)&out[(size_t)bb * (NN * 64) + m * 64 + o] = ov;
                }
            }
        }
        __syncthreads();
    }
}

// ---------------- launch ----------------
extern "C" void kernel_launch(void* const* d_in, const int* in_sizes, int n_in,
                              void* d_out, int out_size) {
    const float* inputs = (const float*)d_in[0];
    const float* hx     = (const float*)d_in[1];
    const float* adj    = (const float*)d_in[2];
    const float* W_ru   = (const float*)d_in[3];
    const float* b_ru   = (const float*)d_in[4];
    const float* W_c    = (const float*)d_in[5];
    const float* b_c    = (const float*)d_in[6];
    float* out = (float*)d_out;

    float *p_XH, *p_RH;
    __half *p_Ah, *p_Bh, *p_Bh2, *p_A1h, *p_A2h, *p_AR1h, *p_AR2h;
    cudaGetSymbolAddress((void**)&p_XH,   g_XH);
    cudaGetSymbolAddress((void**)&p_RH,   g_RH);
    cudaGetSymbolAddress((void**)&p_Ah,   g_Ah);
    cudaGetSymbolAddress((void**)&p_Bh,   g_Bh);
    cudaGetSymbolAddress((void**)&p_Bh2,  g_Bh2);
    cudaGetSymbolAddress((void**)&p_A1h,  g_A1h);
    cudaGetSymbolAddress((void**)&p_A2h,  g_A2h);
    cudaGetSymbolAddress((void**)&p_AR1h, g_AR1h);
    cudaGetSymbolAddress((void**)&p_AR2h, g_AR2h);

    cudaFuncSetAttribute(gemm_mma,    cudaFuncAttributeMaxDynamicSharedMemorySize, GSMEM);
    cudaFuncSetAttribute(proj_ru_mma, cudaFuncAttributeMaxDynamicSharedMemorySize, PRU_SMEM);
    cudaFuncSetAttribute(proj_c_mma,  cudaFuncAttributeMaxDynamicSharedMemorySize, PC_SMEM);

    rowsum_kernel<<<NN, 256>>>(adj);                         // 1
    pack_permW<<<16384 + 288, 256>>>(inputs, hx, W_ru, W_c); // 2
    conv1<<<1024 + 4096, 256>>>(adj);                        // 3

    // 4: A1 = adjT @ XH  -> fp16 A1 + fused fp16 A1^T   (profiled launch)
    gemm_mma<<<dim3(CXH / 128, 16), 512, GSMEM>>>(p_Ah, p_Bh, nullptr, p_A1h, p_Bh2, CXH, 1.0f, 0.0f);
    // 5: A2 = 2*adjT@A1 - XH  -> fp16 A2
    gemm_mma<<<dim3(CXH / 128, 16), 512, GSMEM>>>(p_Ah, p_Bh2, p_XH, p_A2h, nullptr, CXH, 2.0f, -1.0f);

    proj_ru_mma<<<NN / PN, 256, PRU_SMEM>>>(b_ru);           // 6 (emits RH fp32+fp16, U, RH^T fp16)

    // 7: AR1 = adjT @ RH  -> fp16 AR1 + fused fp16 AR1^T
    gemm_mma<<<dim3(C1 / 128, 16), 512, GSMEM>>>(p_Ah, p_Bh, nullptr, p_AR1h, p_Bh2, C1, 1.0f, 0.0f);
    // 8: AR2 = 2*adjT@AR1 - RH  -> fp16 AR2
    gemm_mma<<<dim3(C1 / 128, 16), 512, GSMEM>>>(p_Ah, p_Bh2, p_RH, p_AR2h, nullptr, C1, 2.0f, -1.0f);

    proj_c_mma<<<NN / PN, 256, PC_SMEM>>>(b_c, out);         // 9
}